// round 14
// baseline (speedup 1.0000x reference)
#include <cuda_runtime.h>
#include <cuda_fp16.h>
#include <cstdint>

#define N_TOK 8192
#define DIM   1024

// ---- fp16 mma tile config: CTA 128x128x32, 512 thr, warp tile 32x32, 2 CTA/SM ----
#define BM 128
#define BN 128
#define BK 32
#define NST 5
#define RSH 40                        // halves per smem row (80 B)
#define OPB (128 * RSH * 2)           // 10240 B per operand per stage
#define SS  (2 * OPB)                 // 20480 B per stage
#define PIPE_BYTES (NST * SS)         // 102400 B
#define SMEM_BYTES (PIPE_BYTES + 80)  // + mbarriers

// ---- scratch (device globals; no allocation allowed) ----
__device__ __half g_X [N_TOK * DIM];
__device__ __half g_Q [N_TOK * DIM];
__device__ __half g_K [N_TOK * DIM];
__device__ __half g_VT[N_TOK * DIM];
__device__ __half g_WT[3 * DIM * DIM];                  // [WkT | WqT | WvT]
__device__ __half g_S [(size_t)N_TOK * N_TOK];
__device__ float  g_spart[(size_t)64 * N_TOK];          // score row partial sums
__device__ __half g_opart[(size_t)4 * N_TOK * DIM];     // PV split-K partials (fp16)

// =================== helpers ===================
__device__ __forceinline__ uint32_t smem_u32(const void* p) {
    uint32_t a;
    asm("{ .reg .u64 t; cvta.to.shared.u64 t, %1; cvt.u32.u64 %0, t; }" : "=r"(a) : "l"(p));
    return a;
}
__device__ __forceinline__ void cp16(uint32_t dst, const void* src) {
    asm volatile("cp.async.cg.shared.global [%0], [%1], 16;" :: "r"(dst), "l"(src));
}
__device__ __forceinline__ void mbar_init(uint32_t a, uint32_t c) {
    asm volatile("mbarrier.init.shared.b64 [%0], %1;" :: "r"(a), "r"(c) : "memory");
}
__device__ __forceinline__ void mbar_arrive(uint32_t a) {
    asm volatile("mbarrier.arrive.shared.b64 _, [%0];" :: "r"(a) : "memory");
}
__device__ __forceinline__ void cp_mbar_arrive(uint32_t a) {
    asm volatile("cp.async.mbarrier.arrive.noinc.shared.b64 [%0];" :: "r"(a) : "memory");
}
__device__ __forceinline__ void wait_parity(uint32_t mbar, uint32_t ph) {
    asm volatile(
        "{\n\t.reg .pred P;\n\t"
        "WL%=:\n\t"
        "mbarrier.try_wait.parity.acquire.cta.shared::cta.b64 P, [%0], %1, 0x989680;\n\t"
        "@P bra.uni WD%=;\n\t"
        "bra.uni WL%=;\n\t"
        "WD%=:\n\t}"
        :: "r"(mbar), "r"(ph) : "memory");
}
__device__ __forceinline__ void ldsm4(uint32_t* r, uint32_t addr) {
    asm volatile("ldmatrix.sync.aligned.m8n8.x4.shared.b16 {%0,%1,%2,%3}, [%4];"
                 : "=r"(r[0]), "=r"(r[1]), "=r"(r[2]), "=r"(r[3]) : "r"(addr));
}
__device__ __forceinline__ void mma_f16(float* c, const uint32_t* a, uint32_t b0, uint32_t b1) {
    asm volatile(
        "mma.sync.aligned.m16n8k16.row.col.f32.f16.f16.f32 "
        "{%0,%1,%2,%3}, {%4,%5,%6,%7}, {%8,%9}, {%0,%1,%2,%3};"
        : "+f"(c[0]), "+f"(c[1]), "+f"(c[2]), "+f"(c[3])
        : "r"(a[0]), "r"(a[1]), "r"(a[2]), "r"(a[3]), "r"(b0), "r"(b1));
}

// =================== fp16 mma.sync GEMM (512 thr, warp 32x32, mbarrier pipeline) ===================
// acc = A[M,K_slice] @ B[N,K_slice]^T  (K sliced by gridDim.z)
// MODE 2: C fp16 = exp(alpha*acc); fused row partial sums -> spart
// MODE 4: partial[z] fp16 = acc                 (PV split-K)
// MODE 5: fused QKV projection. blockIdx.x>>3 selects output:
//         0 -> Q fp16, 1 -> K fp16, 2 -> VT fp16 (smem-transposed epilogue).
template<int MODE>
__global__ __launch_bounds__(512, 2)
void gemm_h(const __half* __restrict__ A, const __half* __restrict__ B,
            void* __restrict__ Cv, int M, int N, int K,
            float alpha, float* __restrict__ spart,
            __half* __restrict__ aux1, __half* __restrict__ aux2)
{
    extern __shared__ char smraw[];
    const uint32_t sbase = smem_u32(smraw);
    const uint32_t mb = sbase + PIPE_BYTES;    // full[s]@mb+16s, empty[s]@mb+16s+8
    const int tid  = threadIdx.x;
    const int wid  = tid >> 5, lane = tid & 31;
    const int wm   = wid & 3, wn = wid >> 2;        // 4 x 4 warp grid
    const int rowBase = blockIdx.y * BM;
    const int colBase = blockIdx.x * BN;
    const int kPer = K / gridDim.z;
    const int kOff = blockIdx.z * kPer;
    const int nk = kPer / BK;

    if (tid == 0) {
        #pragma unroll
        for (int s = 0; s < NST; s++) {
            mbar_init(mb + 16 * s, 512);      // full
            mbar_init(mb + 16 * s + 8, 512);  // empty
        }
    }
    __syncthreads();

    // ---- gmem -> smem: 1 cp16 per operand per thread per stage ----
    const int gr = tid >> 2;                 // 0..127
    const int seg = tid & 3;
    const __half* gA = A + (size_t)(rowBase + gr) * K + kOff + seg * 8;
    const __half* gB = B + (size_t)(colBase + gr) * K + kOff + seg * 8;
    const uint32_t dA = sbase + (uint32_t)gr * 80 + seg * 16;
    const uint32_t dB = dA + OPB;

    // ---- ldmatrix base addresses ----
    const int quad = lane >> 3, lr = lane & 7;
    uint32_t aBase[2], bBase[2];
    #pragma unroll
    for (int mt = 0; mt < 2; mt++) {
        int r = wm * 32 + mt * 16 + (quad & 1) * 8 + lr;
        aBase[mt] = sbase + (uint32_t)(r * RSH + (quad >> 1) * 8) * 2;
    }
    #pragma unroll
    for (int p = 0; p < 2; p++) {
        int r = wn * 32 + p * 16 + (quad & 1) * 8 + lr;
        bBase[p] = sbase + OPB + (uint32_t)(r * RSH + (quad >> 1) * 8) * 2;
    }

    float acc[2][4][4];
    #pragma unroll
    for (int i = 0; i < 2; i++)
        #pragma unroll
        for (int j = 0; j < 4; j++)
            #pragma unroll
            for (int e = 0; e < 4; e++) acc[i][j][e] = 0.f;

    // ---- prologue: fill NST-1 stages (no waits: first use of each stage) ----
    #pragma unroll
    for (int s = 0; s < NST - 1; s++) {
        cp16(dA + s * SS, gA);
        cp16(dB + s * SS, gB);
        cp_mbar_arrive(mb + 16 * s);
        gA += BK; gB += BK;
    }

    // ---- main loop: no block barriers; warps drift across stages ----
    int pS = NST - 1, pPh = 1;     // producer cursor (phase flips to 0 on first wrap)
    int cS = 0, cPh = 0;           // consumer cursor
    for (int it = 0; it < nk; it++) {
        const int w = it + NST - 1;
        if (w < nk) {
            if (w >= NST)                      // stage previously used: wait consumers
                wait_parity(mb + 16 * pS + 8, pPh);
            cp16(dA + pS * SS, gA);
            cp16(dB + pS * SS, gB);
            cp_mbar_arrive(mb + 16 * pS);
            gA += BK; gB += BK;
            if (++pS == NST) { pS = 0; pPh ^= 1; }
        }

        wait_parity(mb + 16 * cS, cPh);        // stage data ready
        const uint32_t st = (uint32_t)(cS * SS);
        #pragma unroll
        for (int kk = 0; kk < 2; kk++) {
            const uint32_t off = st + kk * 32;
            uint32_t a[2][4], b[2][4];
            #pragma unroll
            for (int mt = 0; mt < 2; mt++) ldsm4(a[mt], aBase[mt] + off);
            #pragma unroll
            for (int p = 0; p < 2; p++)    ldsm4(b[p],  bBase[p] + off);
            #pragma unroll
            for (int mt = 0; mt < 2; mt++)
                #pragma unroll
                for (int p = 0; p < 2; p++) {
                    mma_f16(acc[mt][2*p],   a[mt], b[p][0], b[p][2]);
                    mma_f16(acc[mt][2*p+1], a[mt], b[p][1], b[p][3]);
                }
        }
        mbar_arrive(mb + 16 * cS + 8);         // release stage for overwrite
        if (++cS == NST) { cS = 0; cPh ^= 1; }
    }

    // ---- epilogue ----
    const int g = lane >> 2, tg = lane & 3;

    if (MODE == 2) {
        float rs0[2] = {0.f, 0.f};
        float rs1[2] = {0.f, 0.f};
        __half* C = (__half*)Cv;
        #pragma unroll
        for (int mt = 0; mt < 2; mt++) {
            const int r0 = rowBase + wm * 32 + mt * 16 + g;
            #pragma unroll
            for (int nt = 0; nt < 4; nt++) {
                const int c = colBase + wn * 32 + nt * 8 + tg * 2;
                float v0 = __expf(alpha * acc[mt][nt][0]);
                float v1 = __expf(alpha * acc[mt][nt][1]);
                float v2 = __expf(alpha * acc[mt][nt][2]);
                float v3 = __expf(alpha * acc[mt][nt][3]);
                rs0[mt] += v0 + v1;
                rs1[mt] += v2 + v3;
                *(__half2*)&C[(size_t)r0 * N + c]       = __floats2half2_rn(v0, v1);
                *(__half2*)&C[(size_t)(r0 + 8) * N + c] = __floats2half2_rn(v2, v3);
            }
        }
        // reduce over tg lanes, then across the 4 wn warps via smem
        float* part = (float*)smraw;           // [4][128]
        __syncthreads();                       // all warps out of mainloop
        #pragma unroll
        for (int mt = 0; mt < 2; mt++) {
            float a0 = rs0[mt], a1 = rs1[mt];
            a0 += __shfl_xor_sync(0xffffffffu, a0, 1);
            a0 += __shfl_xor_sync(0xffffffffu, a0, 2);
            a1 += __shfl_xor_sync(0xffffffffu, a1, 1);
            a1 += __shfl_xor_sync(0xffffffffu, a1, 2);
            if (tg == 0) {
                part[wn * 128 + wm * 32 + mt * 16 + g]     = a0;
                part[wn * 128 + wm * 32 + mt * 16 + g + 8] = a1;
            }
        }
        __syncthreads();
        if (tid < 128) {
            float s = part[tid] + part[128 + tid] + part[256 + tid] + part[384 + tid];
            spart[(size_t)blockIdx.x * M + rowBase + tid] = s;
        }
    } else if (MODE == 5) {
        const int grp = blockIdx.x >> 3;               // 0=Q, 1=K, 2=VT
        const int colLoc = (blockIdx.x & 7) * BN;      // column within 1024
        if (grp < 2) {
            __half* C = grp == 0 ? (__half*)Cv : aux1;
            #pragma unroll
            for (int mt = 0; mt < 2; mt++) {
                const int r0 = rowBase + wm * 32 + mt * 16 + g;
                #pragma unroll
                for (int nt = 0; nt < 4; nt++) {
                    const int c = colLoc + wn * 32 + nt * 8 + tg * 2;
                    *(__half2*)&C[(size_t)r0 * DIM + c] =
                        __floats2half2_rn(acc[mt][nt][0], acc[mt][nt][1]);
                    *(__half2*)&C[(size_t)(r0 + 8) * DIM + c] =
                        __floats2half2_rn(acc[mt][nt][2], acc[mt][nt][3]);
                }
            }
        } else {
            __half* buf = (__half*)smraw;              // [128 cols][136 rows]
            __syncthreads();                           // all warps out of mainloop
            #pragma unroll
            for (int mt = 0; mt < 2; mt++) {
                const int r0 = wm * 32 + mt * 16 + g;
                #pragma unroll
                for (int nt = 0; nt < 4; nt++) {
                    const int c = wn * 32 + nt * 8 + tg * 2;
                    buf[(c    ) * 136 + r0    ] = __float2half_rn(acc[mt][nt][0]);
                    buf[(c + 1) * 136 + r0    ] = __float2half_rn(acc[mt][nt][1]);
                    buf[(c    ) * 136 + r0 + 8] = __float2half_rn(acc[mt][nt][2]);
                    buf[(c + 1) * 136 + r0 + 8] = __float2half_rn(acc[mt][nt][3]);
                }
            }
            __syncthreads();
            __half* VT = aux2;                         // [DIM][N_TOK]
            for (int ch = tid; ch < 128 * 16; ch += 512) {
                const int cc = ch >> 4, sg = ch & 15;
                uint4 v = *(uint4*)&buf[cc * 136 + sg * 8];
                *(uint4*)&VT[(size_t)(colLoc + cc) * M + rowBase + sg * 8] = v;
            }
        }
    } else {  // MODE 4: fp16 split-K partial (fp32 acc, single store rounding)
        __half* C = (__half*)Cv + (size_t)blockIdx.z * M * N;
        #pragma unroll
        for (int mt = 0; mt < 2; mt++) {
            const int r0 = rowBase + wm * 32 + mt * 16 + g;
            #pragma unroll
            for (int nt = 0; nt < 4; nt++) {
                const int c = colBase + wn * 32 + nt * 8 + tg * 2;
                *(__half2*)&C[(size_t)r0 * N + c]       = __floats2half2_rn(acc[mt][nt][0], acc[mt][nt][1]);
                *(__half2*)&C[(size_t)(r0 + 8) * N + c] = __floats2half2_rn(acc[mt][nt][2], acc[mt][nt][3]);
            }
        }
    }
}

// =================== prep: weight transposes (z<3) + x round (z=3) ===================
__global__ void prep_k(const float* __restrict__ x, const float* __restrict__ w0,
                       const float* __restrict__ w1, const float* __restrict__ w2,
                       __half* __restrict__ X, __half* __restrict__ WT)
{
    const int x0 = threadIdx.x, y0 = threadIdx.y;
    if (blockIdx.z < 3) {
        __shared__ float t[32][33];
        const float* in = blockIdx.z == 0 ? w0 : (blockIdx.z == 1 ? w1 : w2);
        __half* o = WT + (size_t)blockIdx.z * DIM * DIM;
        const int c0 = blockIdx.x * 32, r0 = blockIdx.y * 32;
        #pragma unroll
        for (int j = 0; j < 32; j += 8)
            t[y0 + j][x0] = in[(size_t)(r0 + y0 + j) * DIM + c0 + x0];
        __syncthreads();
        #pragma unroll
        for (int j = 0; j < 32; j += 8)
            o[(size_t)(c0 + y0 + j) * DIM + r0 + x0] = __float2half_rn(t[x0][y0 + j]);
    } else {
        // round x -> fp16: 1024 blocks x 256 thr, 8 float4 each
        const int tid = y0 * 32 + x0;
        const int bid = blockIdx.y * 32 + blockIdx.x;
        const float4* in4 = (const float4*)x;
        #pragma unroll
        for (int r = 0; r < 8; r++) {
            const int i = (bid * 8 + r) * 256 + tid;
            float4 v = in4[i];
            __half2* o = (__half2*)(X + (size_t)i * 4);
            o[0] = __floats2half2_rn(v.x, v.y);
            o[1] = __floats2half2_rn(v.z, v.w);
        }
    }
}

// =================== out = rinv[r] * (p0+p1+p2+p3); rinv fused from spart ===================
// block = 256 thr covers 2048 halves = 2 consecutive rows (128 uint4-threads per row)
__global__ __launch_bounds__(256)
void reduce_out(const __half* __restrict__ p, const float* __restrict__ spart,
                float* __restrict__ out)
{
    __shared__ float rinv_s[2];
    const int tid = threadIdx.x;
    const int row0 = blockIdx.x * 2;

    // warps 0,1 compute the two row sums from 64 column-block partials
    if (tid < 64) {
        const int w = tid >> 5, l = tid & 31;
        const int r = row0 + w;
        float s = spart[(size_t)l * N_TOK + r] + spart[(size_t)(l + 32) * N_TOK + r];
        #pragma unroll
        for (int o = 16; o; o >>= 1) s += __shfl_xor_sync(0xffffffffu, s, o);
        if (l == 0) rinv_s[w] = 1.0f / s;
    }
    __syncthreads();

    const size_t i = (size_t)blockIdx.x * 256 + tid;           // uint4 = 8 halves
    const size_t stride = (size_t)N_TOK * DIM / 8;
    const float sc = rinv_s[tid >> 7];
    const uint4* p0 = (const uint4*)p;
    uint4 u0 = p0[i], u1 = p0[i + stride], u2 = p0[i + 2 * stride], u3 = p0[i + 3 * stride];
    float4 o0, o1;
    {
        float2 a = __half22float2(*(__half2*)&u0.x), b = __half22float2(*(__half2*)&u1.x);
        float2 c = __half22float2(*(__half2*)&u2.x), d = __half22float2(*(__half2*)&u3.x);
        o0.x = (a.x + b.x + c.x + d.x) * sc; o0.y = (a.y + b.y + c.y + d.y) * sc;
    }
    {
        float2 a = __half22float2(*(__half2*)&u0.y), b = __half22float2(*(__half2*)&u1.y);
        float2 c = __half22float2(*(__half2*)&u2.y), d = __half22float2(*(__half2*)&u3.y);
        o0.z = (a.x + b.x + c.x + d.x) * sc; o0.w = (a.y + b.y + c.y + d.y) * sc;
    }
    {
        float2 a = __half22float2(*(__half2*)&u0.z), b = __half22float2(*(__half2*)&u1.z);
        float2 c = __half22float2(*(__half2*)&u2.z), d = __half22float2(*(__half2*)&u3.z);
        o1.x = (a.x + b.x + c.x + d.x) * sc; o1.y = (a.y + b.y + c.y + d.y) * sc;
    }
    {
        float2 a = __half22float2(*(__half2*)&u0.w), b = __half22float2(*(__half2*)&u1.w);
        float2 c = __half22float2(*(__half2*)&u2.w), d = __half22float2(*(__half2*)&u3.w);
        o1.z = (a.x + b.x + c.x + d.x) * sc; o1.w = (a.y + b.y + c.y + d.y) * sc;
    }
    ((float4*)out)[i * 2]     = o0;
    ((float4*)out)[i * 2 + 1] = o1;
}

// =================== host ===================
extern "C" void kernel_launch(void* const* d_in, const int* in_sizes, int n_in,
                              void* d_out, int out_size)
{
    const float* x  = (const float*)d_in[0];
    const float* Wq = (const float*)d_in[1];
    const float* Wk = (const float*)d_in[2];
    const float* Wv = (const float*)d_in[3];
    float* out = (float*)d_out;

    __half *X, *Q, *K, *VT, *WT, *S, *Opart;
    float *Spart;
    cudaGetSymbolAddress((void**)&X,     g_X);
    cudaGetSymbolAddress((void**)&Q,     g_Q);
    cudaGetSymbolAddress((void**)&K,     g_K);
    cudaGetSymbolAddress((void**)&VT,    g_VT);
    cudaGetSymbolAddress((void**)&WT,    g_WT);
    cudaGetSymbolAddress((void**)&S,     g_S);
    cudaGetSymbolAddress((void**)&Spart, g_spart);
    cudaGetSymbolAddress((void**)&Opart, g_opart);

    cudaFuncSetAttribute((const void*)gemm_h<2>, cudaFuncAttributeMaxDynamicSharedMemorySize, SMEM_BYTES);
    cudaFuncSetAttribute((const void*)gemm_h<4>, cudaFuncAttributeMaxDynamicSharedMemorySize, SMEM_BYTES);
    cudaFuncSetAttribute((const void*)gemm_h<5>, cudaFuncAttributeMaxDynamicSharedMemorySize, SMEM_BYTES);

    // prep: x -> fp16 and W -> fp16 transposed, packed [WkT|WqT|WvT], one launch
    prep_k<<<dim3(32, 32, 4), dim3(32, 8)>>>(x, Wk, Wq, Wv, X, WT);

    // fused QKV projection (reference name-swap: q = x@Wk, k = x@Wq, v = x@Wv)
    const dim3 gQKV(3 * DIM / BN, N_TOK / BM);     // (24, 64)
    gemm_h<5><<<gQKV, 512, SMEM_BYTES>>>(X, WT, Q, N_TOK, 3 * DIM, DIM, 1.f, nullptr, K, VT);

    // P = exp(QK^T / 32) fp16 + fused row partial sums
    const dim3 gScore(N_TOK / BN, N_TOK / BM);     // (64, 64)
    gemm_h<2><<<gScore, 512, SMEM_BYTES>>>(Q, K, S, N_TOK, N_TOK, DIM, 0.03125f, Spart, nullptr, nullptr);

    // PV split-K=4 -> fp16 partials, then fused rinv + reduce + normalize
    const dim3 gPV(DIM / BN, N_TOK / BM, 4);       // (8, 64, 4)
    gemm_h<4><<<gPV, 512, SMEM_BYTES>>>(S, VT, Opart, N_TOK, DIM, N_TOK, 1.f, nullptr, nullptr, nullptr);
    reduce_out<<<N_TOK / 2, 256>>>(Opart, Spart, out);
}

// round 15
// speedup vs baseline: 1.0563x; 1.0563x over previous
#include <cuda_runtime.h>
#include <cuda_fp16.h>
#include <cstdint>

#define N_TOK 8192
#define DIM   1024

// ---- fp16 mma tile config: CTA 128x128x32, 512 thr, warp tile 32x32, 2 CTA/SM ----
#define BM 128
#define BN 128
#define BK 32
#define NST 4
#define RSH 40                        // halves per smem row (80 B)
#define OPB (128 * RSH * 2)           // 10240 B per operand per stage
#define SS  (2 * OPB)                 // 20480 B per stage
#define PIPE_BYTES (NST * SS)         // 81920 B
#define SMEM_BYTES (PIPE_BYTES + 64)  // + mbarriers

// ---- scratch (device globals; no allocation allowed) ----
__device__ __half g_X [N_TOK * DIM];
__device__ __half g_Q [N_TOK * DIM];
__device__ __half g_K [N_TOK * DIM];
__device__ __half g_VT[N_TOK * DIM];
__device__ __half g_WT[3 * DIM * DIM];                  // [WkT | WqT | WvT]
__device__ __half g_S [(size_t)N_TOK * N_TOK];
__device__ float  g_spart[(size_t)64 * N_TOK];          // score row partial sums
__device__ __half g_opart[(size_t)4 * N_TOK * DIM];     // PV split-K partials (fp16)

// =================== helpers ===================
__device__ __forceinline__ uint32_t smem_u32(const void* p) {
    uint32_t a;
    asm("{ .reg .u64 t; cvta.to.shared.u64 t, %1; cvt.u32.u64 %0, t; }" : "=r"(a) : "l"(p));
    return a;
}
__device__ __forceinline__ void cp16(uint32_t dst, const void* src) {
    asm volatile("cp.async.cg.shared.global [%0], [%1], 16;" :: "r"(dst), "l"(src));
}
__device__ __forceinline__ void mbar_init(uint32_t a, uint32_t c) {
    asm volatile("mbarrier.init.shared.b64 [%0], %1;" :: "r"(a), "r"(c) : "memory");
}
__device__ __forceinline__ void mbar_arrive(uint32_t a) {
    asm volatile("mbarrier.arrive.shared.b64 _, [%0];" :: "r"(a) : "memory");
}
__device__ __forceinline__ void cp_mbar_arrive(uint32_t a) {
    asm volatile("cp.async.mbarrier.arrive.noinc.shared.b64 [%0];" :: "r"(a) : "memory");
}
__device__ __forceinline__ void wait_parity(uint32_t mbar, uint32_t ph) {
    asm volatile(
        "{\n\t.reg .pred P;\n\t"
        "WL%=:\n\t"
        "mbarrier.try_wait.parity.acquire.cta.shared::cta.b64 P, [%0], %1, 0x989680;\n\t"
        "@P bra.uni WD%=;\n\t"
        "bra.uni WL%=;\n\t"
        "WD%=:\n\t}"
        :: "r"(mbar), "r"(ph) : "memory");
}
__device__ __forceinline__ void ldsm4(uint32_t* r, uint32_t addr) {
    asm volatile("ldmatrix.sync.aligned.m8n8.x4.shared.b16 {%0,%1,%2,%3}, [%4];"
                 : "=r"(r[0]), "=r"(r[1]), "=r"(r[2]), "=r"(r[3]) : "r"(addr));
}
__device__ __forceinline__ void mma_f16(float* c, const uint32_t* a, uint32_t b0, uint32_t b1) {
    asm volatile(
        "mma.sync.aligned.m16n8k16.row.col.f32.f16.f16.f32 "
        "{%0,%1,%2,%3}, {%4,%5,%6,%7}, {%8,%9}, {%0,%1,%2,%3};"
        : "+f"(c[0]), "+f"(c[1]), "+f"(c[2]), "+f"(c[3])
        : "r"(a[0]), "r"(a[1]), "r"(a[2]), "r"(a[3]), "r"(b0), "r"(b1));
}

// =================== fp16 mma.sync GEMM (512 thr, warp 32x32, mbarrier pipeline) ===================
// acc = A[M,K_slice] @ B[N,K_slice]^T  (K sliced by gridDim.z)
// MODE 2: C fp16 = exp(alpha*acc); fused row partial sums -> spart
// MODE 4: partial[z] fp16 = acc                 (PV split-K)
// MODE 5: fused QKV projection. blockIdx.x>>3 selects output:
//         0 -> Q fp16, 1 -> K fp16, 2 -> VT fp16 (smem-transposed epilogue).
template<int MODE>
__global__ __launch_bounds__(512, 2)
void gemm_h(const __half* __restrict__ A, const __half* __restrict__ B,
            void* __restrict__ Cv, int M, int N, int K,
            float alpha, float* __restrict__ spart,
            __half* __restrict__ aux1, __half* __restrict__ aux2)
{
    extern __shared__ char smraw[];
    const uint32_t sbase = smem_u32(smraw);
    const uint32_t mb = sbase + PIPE_BYTES;    // full[s]@mb+16s, empty[s]@mb+16s+8
    const int tid  = threadIdx.x;
    const int wid  = tid >> 5, lane = tid & 31;
    const int wm   = wid & 3, wn = wid >> 2;        // 4 x 4 warp grid
    const int rowBase = blockIdx.y * BM;
    const int colBase = blockIdx.x * BN;
    const int kPer = K / gridDim.z;
    const int kOff = blockIdx.z * kPer;
    const int nk = kPer / BK;

    if (tid == 0) {
        #pragma unroll
        for (int s = 0; s < NST; s++) {
            mbar_init(mb + 16 * s, 512);      // full
            mbar_init(mb + 16 * s + 8, 512);  // empty
        }
    }
    __syncthreads();

    // ---- gmem -> smem: 1 cp16 per operand per thread per stage ----
    const int gr = tid >> 2;                 // 0..127
    const int seg = tid & 3;
    const __half* gA = A + (size_t)(rowBase + gr) * K + kOff + seg * 8;
    const __half* gB = B + (size_t)(colBase + gr) * K + kOff + seg * 8;
    const uint32_t dA = sbase + (uint32_t)gr * 80 + seg * 16;
    const uint32_t dB = dA + OPB;

    // ---- ldmatrix base addresses ----
    const int quad = lane >> 3, lr = lane & 7;
    uint32_t aBase[2], bBase[2];
    #pragma unroll
    for (int mt = 0; mt < 2; mt++) {
        int r = wm * 32 + mt * 16 + (quad & 1) * 8 + lr;
        aBase[mt] = sbase + (uint32_t)(r * RSH + (quad >> 1) * 8) * 2;
    }
    #pragma unroll
    for (int p = 0; p < 2; p++) {
        int r = wn * 32 + p * 16 + (quad & 1) * 8 + lr;
        bBase[p] = sbase + OPB + (uint32_t)(r * RSH + (quad >> 1) * 8) * 2;
    }

    float acc[2][4][4];
    #pragma unroll
    for (int i = 0; i < 2; i++)
        #pragma unroll
        for (int j = 0; j < 4; j++)
            #pragma unroll
            for (int e = 0; e < 4; e++) acc[i][j][e] = 0.f;

    // ---- prologue: fill NST-1 stages (no waits: first use of each stage) ----
    #pragma unroll
    for (int s = 0; s < NST - 1; s++) {
        cp16(dA + s * SS, gA);
        cp16(dB + s * SS, gB);
        cp_mbar_arrive(mb + 16 * s);
        gA += BK; gB += BK;
    }

    // ---- main loop: no block barriers; warps drift across stages ----
    int pS = NST - 1, pPh = 1;     // producer cursor (phase flips to 0 on first wrap)
    int cS = 0, cPh = 0;           // consumer cursor
    for (int it = 0; it < nk; it++) {
        const int w = it + NST - 1;
        if (w < nk) {
            if (w >= NST)                      // stage previously used: wait consumers
                wait_parity(mb + 16 * pS + 8, pPh);
            cp16(dA + pS * SS, gA);
            cp16(dB + pS * SS, gB);
            cp_mbar_arrive(mb + 16 * pS);
            gA += BK; gB += BK;
            if (++pS == NST) { pS = 0; pPh ^= 1; }
        }

        wait_parity(mb + 16 * cS, cPh);        // stage data ready
        const uint32_t st = (uint32_t)(cS * SS);
        #pragma unroll
        for (int kk = 0; kk < 2; kk++) {
            const uint32_t off = st + kk * 32;
            uint32_t a[2][4], b[2][4];
            #pragma unroll
            for (int mt = 0; mt < 2; mt++) ldsm4(a[mt], aBase[mt] + off);
            #pragma unroll
            for (int p = 0; p < 2; p++)    ldsm4(b[p],  bBase[p] + off);
            #pragma unroll
            for (int mt = 0; mt < 2; mt++)
                #pragma unroll
                for (int p = 0; p < 2; p++) {
                    mma_f16(acc[mt][2*p],   a[mt], b[p][0], b[p][2]);
                    mma_f16(acc[mt][2*p+1], a[mt], b[p][1], b[p][3]);
                }
        }
        mbar_arrive(mb + 16 * cS + 8);         // release stage for overwrite
        if (++cS == NST) { cS = 0; cPh ^= 1; }
    }

    // ---- epilogue ----
    const int g = lane >> 2, tg = lane & 3;

    if (MODE == 2) {
        float rs0[2] = {0.f, 0.f};
        float rs1[2] = {0.f, 0.f};
        __half* C = (__half*)Cv;
        #pragma unroll
        for (int mt = 0; mt < 2; mt++) {
            const int r0 = rowBase + wm * 32 + mt * 16 + g;
            #pragma unroll
            for (int nt = 0; nt < 4; nt++) {
                const int c = colBase + wn * 32 + nt * 8 + tg * 2;
                float v0 = __expf(alpha * acc[mt][nt][0]);
                float v1 = __expf(alpha * acc[mt][nt][1]);
                float v2 = __expf(alpha * acc[mt][nt][2]);
                float v3 = __expf(alpha * acc[mt][nt][3]);
                rs0[mt] += v0 + v1;
                rs1[mt] += v2 + v3;
                *(__half2*)&C[(size_t)r0 * N + c]       = __floats2half2_rn(v0, v1);
                *(__half2*)&C[(size_t)(r0 + 8) * N + c] = __floats2half2_rn(v2, v3);
            }
        }
        // reduce over tg lanes, then across the 4 wn warps via smem
        float* part = (float*)smraw;           // [4][128]
        __syncthreads();                       // all warps out of mainloop
        #pragma unroll
        for (int mt = 0; mt < 2; mt++) {
            float a0 = rs0[mt], a1 = rs1[mt];
            a0 += __shfl_xor_sync(0xffffffffu, a0, 1);
            a0 += __shfl_xor_sync(0xffffffffu, a0, 2);
            a1 += __shfl_xor_sync(0xffffffffu, a1, 1);
            a1 += __shfl_xor_sync(0xffffffffu, a1, 2);
            if (tg == 0) {
                part[wn * 128 + wm * 32 + mt * 16 + g]     = a0;
                part[wn * 128 + wm * 32 + mt * 16 + g + 8] = a1;
            }
        }
        __syncthreads();
        if (tid < 128) {
            float s = part[tid] + part[128 + tid] + part[256 + tid] + part[384 + tid];
            spart[(size_t)blockIdx.x * M + rowBase + tid] = s;
        }
    } else if (MODE == 5) {
        const int grp = blockIdx.x >> 3;               // 0=Q, 1=K, 2=VT
        const int colLoc = (blockIdx.x & 7) * BN;      // column within 1024
        if (grp < 2) {
            __half* C = grp == 0 ? (__half*)Cv : aux1;
            #pragma unroll
            for (int mt = 0; mt < 2; mt++) {
                const int r0 = rowBase + wm * 32 + mt * 16 + g;
                #pragma unroll
                for (int nt = 0; nt < 4; nt++) {
                    const int c = colLoc + wn * 32 + nt * 8 + tg * 2;
                    *(__half2*)&C[(size_t)r0 * DIM + c] =
                        __floats2half2_rn(acc[mt][nt][0], acc[mt][nt][1]);
                    *(__half2*)&C[(size_t)(r0 + 8) * DIM + c] =
                        __floats2half2_rn(acc[mt][nt][2], acc[mt][nt][3]);
                }
            }
        } else {
            __half* buf = (__half*)smraw;              // [128 cols][136 rows]
            __syncthreads();                           // all warps out of mainloop
            #pragma unroll
            for (int mt = 0; mt < 2; mt++) {
                const int r0 = wm * 32 + mt * 16 + g;
                #pragma unroll
                for (int nt = 0; nt < 4; nt++) {
                    const int c = wn * 32 + nt * 8 + tg * 2;
                    buf[(c    ) * 136 + r0    ] = __float2half_rn(acc[mt][nt][0]);
                    buf[(c + 1) * 136 + r0    ] = __float2half_rn(acc[mt][nt][1]);
                    buf[(c    ) * 136 + r0 + 8] = __float2half_rn(acc[mt][nt][2]);
                    buf[(c + 1) * 136 + r0 + 8] = __float2half_rn(acc[mt][nt][3]);
                }
            }
            __syncthreads();
            __half* VT = aux2;                         // [DIM][N_TOK]
            for (int ch = tid; ch < 128 * 16; ch += 512) {
                const int cc = ch >> 4, sg = ch & 15;
                uint4 v = *(uint4*)&buf[cc * 136 + sg * 8];
                *(uint4*)&VT[(size_t)(colLoc + cc) * M + rowBase + sg * 8] = v;
            }
        }
    } else {  // MODE 4: fp16 split-K partial (fp32 acc, single store rounding)
        __half* C = (__half*)Cv + (size_t)blockIdx.z * M * N;
        #pragma unroll
        for (int mt = 0; mt < 2; mt++) {
            const int r0 = rowBase + wm * 32 + mt * 16 + g;
            #pragma unroll
            for (int nt = 0; nt < 4; nt++) {
                const int c = colBase + wn * 32 + nt * 8 + tg * 2;
                *(__half2*)&C[(size_t)r0 * N + c]       = __floats2half2_rn(acc[mt][nt][0], acc[mt][nt][1]);
                *(__half2*)&C[(size_t)(r0 + 8) * N + c] = __floats2half2_rn(acc[mt][nt][2], acc[mt][nt][3]);
            }
        }
    }
}

// =================== prep: weight transposes (z<3) + x round (z=3) ===================
__global__ void prep_k(const float* __restrict__ x, const float* __restrict__ w0,
                       const float* __restrict__ w1, const float* __restrict__ w2,
                       __half* __restrict__ X, __half* __restrict__ WT)
{
    const int x0 = threadIdx.x, y0 = threadIdx.y;
    if (blockIdx.z < 3) {
        __shared__ float t[32][33];
        const float* in = blockIdx.z == 0 ? w0 : (blockIdx.z == 1 ? w1 : w2);
        __half* o = WT + (size_t)blockIdx.z * DIM * DIM;
        const int c0 = blockIdx.x * 32, r0 = blockIdx.y * 32;
        #pragma unroll
        for (int j = 0; j < 32; j += 8)
            t[y0 + j][x0] = in[(size_t)(r0 + y0 + j) * DIM + c0 + x0];
        __syncthreads();
        #pragma unroll
        for (int j = 0; j < 32; j += 8)
            o[(size_t)(c0 + y0 + j) * DIM + r0 + x0] = __float2half_rn(t[x0][y0 + j]);
    } else {
        // round x -> fp16: 1024 blocks x 256 thr, 8 float4 each
        const int tid = y0 * 32 + x0;
        const int bid = blockIdx.y * 32 + blockIdx.x;
        const float4* in4 = (const float4*)x;
        #pragma unroll
        for (int r = 0; r < 8; r++) {
            const int i = (bid * 8 + r) * 256 + tid;
            float4 v = in4[i];
            __half2* o = (__half2*)(X + (size_t)i * 4);
            o[0] = __floats2half2_rn(v.x, v.y);
            o[1] = __floats2half2_rn(v.z, v.w);
        }
    }
}

// =================== out = rinv[r] * (p0+p1+p2+p3); rinv fused from spart ===================
// block = 256 thr covers 2048 halves = 2 consecutive rows (128 uint4-threads per row)
__global__ __launch_bounds__(256)
void reduce_out(const __half* __restrict__ p, const float* __restrict__ spart,
                float* __restrict__ out)
{
    __shared__ float rinv_s[2];
    const int tid = threadIdx.x;
    const int row0 = blockIdx.x * 2;

    // warps 0,1 compute the two row sums from 64 column-block partials
    if (tid < 64) {
        const int w = tid >> 5, l = tid & 31;
        const int r = row0 + w;
        float s = spart[(size_t)l * N_TOK + r] + spart[(size_t)(l + 32) * N_TOK + r];
        #pragma unroll
        for (int o = 16; o; o >>= 1) s += __shfl_xor_sync(0xffffffffu, s, o);
        if (l == 0) rinv_s[w] = 1.0f / s;
    }
    __syncthreads();

    const size_t i = (size_t)blockIdx.x * 256 + tid;           // uint4 = 8 halves
    const size_t stride = (size_t)N_TOK * DIM / 8;
    const float sc = rinv_s[tid >> 7];
    const uint4* p0 = (const uint4*)p;
    uint4 u0 = p0[i], u1 = p0[i + stride], u2 = p0[i + 2 * stride], u3 = p0[i + 3 * stride];
    float4 o0, o1;
    {
        float2 a = __half22float2(*(__half2*)&u0.x), b = __half22float2(*(__half2*)&u1.x);
        float2 c = __half22float2(*(__half2*)&u2.x), d = __half22float2(*(__half2*)&u3.x);
        o0.x = (a.x + b.x + c.x + d.x) * sc; o0.y = (a.y + b.y + c.y + d.y) * sc;
    }
    {
        float2 a = __half22float2(*(__half2*)&u0.y), b = __half22float2(*(__half2*)&u1.y);
        float2 c = __half22float2(*(__half2*)&u2.y), d = __half22float2(*(__half2*)&u3.y);
        o0.z = (a.x + b.x + c.x + d.x) * sc; o0.w = (a.y + b.y + c.y + d.y) * sc;
    }
    {
        float2 a = __half22float2(*(__half2*)&u0.z), b = __half22float2(*(__half2*)&u1.z);
        float2 c = __half22float2(*(__half2*)&u2.z), d = __half22float2(*(__half2*)&u3.z);
        o1.x = (a.x + b.x + c.x + d.x) * sc; o1.y = (a.y + b.y + c.y + d.y) * sc;
    }
    {
        float2 a = __half22float2(*(__half2*)&u0.w), b = __half22float2(*(__half2*)&u1.w);
        float2 c = __half22float2(*(__half2*)&u2.w), d = __half22float2(*(__half2*)&u3.w);
        o1.z = (a.x + b.x + c.x + d.x) * sc; o1.w = (a.y + b.y + c.y + d.y) * sc;
    }
    ((float4*)out)[i * 2]     = o0;
    ((float4*)out)[i * 2 + 1] = o1;
}

// =================== host ===================
extern "C" void kernel_launch(void* const* d_in, const int* in_sizes, int n_in,
                              void* d_out, int out_size)
{
    const float* x  = (const float*)d_in[0];
    const float* Wq = (const float*)d_in[1];
    const float* Wk = (const float*)d_in[2];
    const float* Wv = (const float*)d_in[3];
    float* out = (float*)d_out;

    __half *X, *Q, *K, *VT, *WT, *S, *Opart;
    float *Spart;
    cudaGetSymbolAddress((void**)&X,     g_X);
    cudaGetSymbolAddress((void**)&Q,     g_Q);
    cudaGetSymbolAddress((void**)&K,     g_K);
    cudaGetSymbolAddress((void**)&VT,    g_VT);
    cudaGetSymbolAddress((void**)&WT,    g_WT);
    cudaGetSymbolAddress((void**)&S,     g_S);
    cudaGetSymbolAddress((void**)&Spart, g_spart);
    cudaGetSymbolAddress((void**)&Opart, g_opart);

    cudaFuncSetAttribute((const void*)gemm_h<2>, cudaFuncAttributeMaxDynamicSharedMemorySize, SMEM_BYTES);
    cudaFuncSetAttribute((const void*)gemm_h<4>, cudaFuncAttributeMaxDynamicSharedMemorySize, SMEM_BYTES);
    cudaFuncSetAttribute((const void*)gemm_h<5>, cudaFuncAttributeMaxDynamicSharedMemorySize, SMEM_BYTES);

    // prep: x -> fp16 and W -> fp16 transposed, packed [WkT|WqT|WvT], one launch
    prep_k<<<dim3(32, 32, 4), dim3(32, 8)>>>(x, Wk, Wq, Wv, X, WT);

    // fused QKV projection (reference name-swap: q = x@Wk, k = x@Wq, v = x@Wv)
    const dim3 gQKV(3 * DIM / BN, N_TOK / BM);     // (24, 64)
    gemm_h<5><<<gQKV, 512, SMEM_BYTES>>>(X, WT, Q, N_TOK, 3 * DIM, DIM, 1.f, nullptr, K, VT);

    // P = exp(QK^T / 32) fp16 + fused row partial sums
    const dim3 gScore(N_TOK / BN, N_TOK / BM);     // (64, 64)
    gemm_h<2><<<gScore, 512, SMEM_BYTES>>>(Q, K, S, N_TOK, N_TOK, DIM, 0.03125f, Spart, nullptr, nullptr);

    // PV split-K=4 -> fp16 partials, then fused rinv + reduce + normalize
    const dim3 gPV(DIM / BN, N_TOK / BM, 4);       // (8, 64, 4)
    gemm_h<4><<<gPV, 512, SMEM_BYTES>>>(S, VT, Opart, N_TOK, DIM, N_TOK, 1.f, nullptr, nullptr, nullptr);
    reduce_out<<<N_TOK / 2, 256>>>(Opart, Spart, out);
}

// round 16
// speedup vs baseline: 1.0957x; 1.0373x over previous
#include <cuda_runtime.h>
#include <cuda_fp16.h>
#include <cstdint>

#define N_TOK 8192
#define DIM   1024

// ---- fp16 mma tile config: CTA 128x128x64, 512 thr, warp tile 32x32, 2 CTA/SM ----
#define BM 128
#define BN 128
#define BK 64
#define NST 2
#define RSH 72                        // halves per smem row (144 B: 128 data + 16 pad)
#define OPB (128 * RSH * 2)           // 18432 B per operand per stage
#define SS  (2 * OPB)                 // 36864 B per stage
#define PIPE_BYTES (NST * SS)         // 73728 B
#define SMEM_BYTES (PIPE_BYTES + 64)  // + mbarriers

// ---- scratch (device globals; no allocation allowed) ----
__device__ __half g_X [N_TOK * DIM];
__device__ __half g_Q [N_TOK * DIM];
__device__ __half g_K [N_TOK * DIM];
__device__ __half g_VT[N_TOK * DIM];
__device__ __half g_WT[3 * DIM * DIM];                  // [WkT | WqT | WvT]
__device__ __half g_S [(size_t)N_TOK * N_TOK];
__device__ float  g_spart[(size_t)64 * N_TOK];          // score row partial sums
__device__ __half g_opart[(size_t)4 * N_TOK * DIM];     // PV split-K partials (fp16)

// =================== helpers ===================
__device__ __forceinline__ uint32_t smem_u32(const void* p) {
    uint32_t a;
    asm("{ .reg .u64 t; cvta.to.shared.u64 t, %1; cvt.u32.u64 %0, t; }" : "=r"(a) : "l"(p));
    return a;
}
__device__ __forceinline__ void cp16(uint32_t dst, const void* src) {
    asm volatile("cp.async.cg.shared.global [%0], [%1], 16;" :: "r"(dst), "l"(src));
}
__device__ __forceinline__ void mbar_init(uint32_t a, uint32_t c) {
    asm volatile("mbarrier.init.shared.b64 [%0], %1;" :: "r"(a), "r"(c) : "memory");
}
__device__ __forceinline__ void mbar_arrive(uint32_t a) {
    asm volatile("mbarrier.arrive.shared.b64 _, [%0];" :: "r"(a) : "memory");
}
__device__ __forceinline__ void cp_mbar_arrive(uint32_t a) {
    asm volatile("cp.async.mbarrier.arrive.noinc.shared.b64 [%0];" :: "r"(a) : "memory");
}
__device__ __forceinline__ void wait_parity(uint32_t mbar, uint32_t ph) {
    asm volatile(
        "{\n\t.reg .pred P;\n\t"
        "WL%=:\n\t"
        "mbarrier.try_wait.parity.acquire.cta.shared::cta.b64 P, [%0], %1, 0x989680;\n\t"
        "@P bra.uni WD%=;\n\t"
        "bra.uni WL%=;\n\t"
        "WD%=:\n\t}"
        :: "r"(mbar), "r"(ph) : "memory");
}
__device__ __forceinline__ void ldsm4(uint32_t* r, uint32_t addr) {
    asm volatile("ldmatrix.sync.aligned.m8n8.x4.shared.b16 {%0,%1,%2,%3}, [%4];"
                 : "=r"(r[0]), "=r"(r[1]), "=r"(r[2]), "=r"(r[3]) : "r"(addr));
}
__device__ __forceinline__ void mma_f16(float* c, const uint32_t* a, uint32_t b0, uint32_t b1) {
    asm volatile(
        "mma.sync.aligned.m16n8k16.row.col.f32.f16.f16.f32 "
        "{%0,%1,%2,%3}, {%4,%5,%6,%7}, {%8,%9}, {%0,%1,%2,%3};"
        : "+f"(c[0]), "+f"(c[1]), "+f"(c[2]), "+f"(c[3])
        : "r"(a[0]), "r"(a[1]), "r"(a[2]), "r"(a[3]), "r"(b0), "r"(b1));
}

// =================== fp16 mma.sync GEMM (512 thr, warp 32x32, BK=64, mbarrier drift) ===================
// acc = A[M,K_slice] @ B[N,K_slice]^T  (K sliced by gridDim.z)
// MODE 2: C fp16 = exp(alpha*acc); fused row partial sums -> spart
// MODE 4: partial[z] fp16 = acc                 (PV split-K)
// MODE 5: fused QKV projection. blockIdx.x>>3 selects output:
//         0 -> Q fp16, 1 -> K fp16, 2 -> VT fp16 (smem-transposed epilogue).
template<int MODE>
__global__ __launch_bounds__(512, 2)
void gemm_h(const __half* __restrict__ A, const __half* __restrict__ B,
            void* __restrict__ Cv, int M, int N, int K,
            float alpha, float* __restrict__ spart,
            __half* __restrict__ aux1, __half* __restrict__ aux2)
{
    extern __shared__ char smraw[];
    const uint32_t sbase = smem_u32(smraw);
    const uint32_t mb = sbase + PIPE_BYTES;    // full[s]@mb+16s, empty[s]@mb+16s+8
    const int tid  = threadIdx.x;
    const int wid  = tid >> 5, lane = tid & 31;
    const int wm   = wid & 3, wn = wid >> 2;        // 4 x 4 warp grid
    const int rowBase = blockIdx.y * BM;
    const int colBase = blockIdx.x * BN;
    const int kPer = K / gridDim.z;
    const int kOff = blockIdx.z * kPer;
    const int nk = kPer / BK;

    if (tid == 0) {
        #pragma unroll
        for (int s = 0; s < NST; s++) {
            mbar_init(mb + 16 * s, 512);      // full
            mbar_init(mb + 16 * s + 8, 512);  // empty
        }
    }
    __syncthreads();

    // ---- gmem -> smem: 128B rows, 8 x 16B segments; 2 row-groups per operand ----
    const int gr = tid >> 3;                 // 0..63
    const int seg = tid & 7;                 // 0..7
    const __half* gA = A + (size_t)(rowBase + gr) * K + kOff + seg * 8;
    const __half* gB = B + (size_t)(colBase + gr) * K + kOff + seg * 8;
    const size_t hop = (size_t)64 * K;
    const uint32_t dA = sbase + (uint32_t)gr * 144 + seg * 16;
    const uint32_t dB = dA + OPB;

    // ---- ldmatrix base addresses ----
    const int quad = lane >> 3, lr = lane & 7;
    uint32_t aBase[2], bBase[2];
    #pragma unroll
    for (int mt = 0; mt < 2; mt++) {
        int r = wm * 32 + mt * 16 + (quad & 1) * 8 + lr;
        aBase[mt] = sbase + (uint32_t)(r * RSH + (quad >> 1) * 8) * 2;
    }
    #pragma unroll
    for (int p = 0; p < 2; p++) {
        int r = wn * 32 + p * 16 + (quad & 1) * 8 + lr;
        bBase[p] = sbase + OPB + (uint32_t)(r * RSH + (quad >> 1) * 8) * 2;
    }

    float acc[2][4][4];
    #pragma unroll
    for (int i = 0; i < 2; i++)
        #pragma unroll
        for (int j = 0; j < 4; j++)
            #pragma unroll
            for (int e = 0; e < 4; e++) acc[i][j][e] = 0.f;

    // ---- prologue: fill NST-1 stages ----
    #pragma unroll
    for (int s = 0; s < NST - 1; s++) {
        cp16(dA + s * SS,            gA);
        cp16(dA + s * SS + 64 * 144, gA + hop);
        cp16(dB + s * SS,            gB);
        cp16(dB + s * SS + 64 * 144, gB + hop);
        cp_mbar_arrive(mb + 16 * s);
        gA += BK; gB += BK;
    }

    // ---- main loop: no block barriers; warps drift across stages ----
    int pS = NST - 1, pPh = 1;     // producer cursor
    int cS = 0, cPh = 0;           // consumer cursor
    for (int it = 0; it < nk; it++) {
        const int w = it + NST - 1;
        if (w < nk) {
            if (w >= NST)                      // stage previously used: wait consumers
                wait_parity(mb + 16 * pS + 8, pPh);
            cp16(dA + pS * SS,            gA);
            cp16(dA + pS * SS + 64 * 144, gA + hop);
            cp16(dB + pS * SS,            gB);
            cp16(dB + pS * SS + 64 * 144, gB + hop);
            cp_mbar_arrive(mb + 16 * pS);
            gA += BK; gB += BK;
            if (++pS == NST) { pS = 0; pPh ^= 1; }
        }

        wait_parity(mb + 16 * cS, cPh);        // stage data ready
        const uint32_t st = (uint32_t)(cS * SS);
        #pragma unroll
        for (int kk = 0; kk < 4; kk++) {       // 4 x k16 per stage
            const uint32_t off = st + kk * 32;
            uint32_t a[2][4], b[2][4];
            #pragma unroll
            for (int mt = 0; mt < 2; mt++) ldsm4(a[mt], aBase[mt] + off);
            #pragma unroll
            for (int p = 0; p < 2; p++)    ldsm4(b[p],  bBase[p] + off);
            #pragma unroll
            for (int mt = 0; mt < 2; mt++)
                #pragma unroll
                for (int p = 0; p < 2; p++) {
                    mma_f16(acc[mt][2*p],   a[mt], b[p][0], b[p][2]);
                    mma_f16(acc[mt][2*p+1], a[mt], b[p][1], b[p][3]);
                }
        }
        mbar_arrive(mb + 16 * cS + 8);         // release stage for overwrite
        if (++cS == NST) { cS = 0; cPh ^= 1; }
    }

    // ---- epilogue ----
    const int g = lane >> 2, tg = lane & 3;

    if (MODE == 2) {
        float rs0[2] = {0.f, 0.f};
        float rs1[2] = {0.f, 0.f};
        __half* C = (__half*)Cv;
        #pragma unroll
        for (int mt = 0; mt < 2; mt++) {
            const int r0 = rowBase + wm * 32 + mt * 16 + g;
            #pragma unroll
            for (int nt = 0; nt < 4; nt++) {
                const int c = colBase + wn * 32 + nt * 8 + tg * 2;
                float v0 = __expf(alpha * acc[mt][nt][0]);
                float v1 = __expf(alpha * acc[mt][nt][1]);
                float v2 = __expf(alpha * acc[mt][nt][2]);
                float v3 = __expf(alpha * acc[mt][nt][3]);
                rs0[mt] += v0 + v1;
                rs1[mt] += v2 + v3;
                *(__half2*)&C[(size_t)r0 * N + c]       = __floats2half2_rn(v0, v1);
                *(__half2*)&C[(size_t)(r0 + 8) * N + c] = __floats2half2_rn(v2, v3);
            }
        }
        // reduce over tg lanes, then across the 4 wn warps via smem
        float* part = (float*)smraw;           // [4][128]
        __syncthreads();                       // all warps out of mainloop
        #pragma unroll
        for (int mt = 0; mt < 2; mt++) {
            float a0 = rs0[mt], a1 = rs1[mt];
            a0 += __shfl_xor_sync(0xffffffffu, a0, 1);
            a0 += __shfl_xor_sync(0xffffffffu, a0, 2);
            a1 += __shfl_xor_sync(0xffffffffu, a1, 1);
            a1 += __shfl_xor_sync(0xffffffffu, a1, 2);
            if (tg == 0) {
                part[wn * 128 + wm * 32 + mt * 16 + g]     = a0;
                part[wn * 128 + wm * 32 + mt * 16 + g + 8] = a1;
            }
        }
        __syncthreads();
        if (tid < 128) {
            float s = part[tid] + part[128 + tid] + part[256 + tid] + part[384 + tid];
            spart[(size_t)blockIdx.x * M + rowBase + tid] = s;
        }
    } else if (MODE == 5) {
        const int grp = blockIdx.x >> 3;               // 0=Q, 1=K, 2=VT
        const int colLoc = (blockIdx.x & 7) * BN;      // column within 1024
        if (grp < 2) {
            __half* C = grp == 0 ? (__half*)Cv : aux1;
            #pragma unroll
            for (int mt = 0; mt < 2; mt++) {
                const int r0 = rowBase + wm * 32 + mt * 16 + g;
                #pragma unroll
                for (int nt = 0; nt < 4; nt++) {
                    const int c = colLoc + wn * 32 + nt * 8 + tg * 2;
                    *(__half2*)&C[(size_t)r0 * DIM + c] =
                        __floats2half2_rn(acc[mt][nt][0], acc[mt][nt][1]);
                    *(__half2*)&C[(size_t)(r0 + 8) * DIM + c] =
                        __floats2half2_rn(acc[mt][nt][2], acc[mt][nt][3]);
                }
            }
        } else {
            __half* buf = (__half*)smraw;              // [128 cols][136 rows]
            __syncthreads();                           // all warps out of mainloop
            #pragma unroll
            for (int mt = 0; mt < 2; mt++) {
                const int r0 = wm * 32 + mt * 16 + g;
                #pragma unroll
                for (int nt = 0; nt < 4; nt++) {
                    const int c = wn * 32 + nt * 8 + tg * 2;
                    buf[(c    ) * 136 + r0    ] = __float2half_rn(acc[mt][nt][0]);
                    buf[(c + 1) * 136 + r0    ] = __float2half_rn(acc[mt][nt][1]);
                    buf[(c    ) * 136 + r0 + 8] = __float2half_rn(acc[mt][nt][2]);
                    buf[(c + 1) * 136 + r0 + 8] = __float2half_rn(acc[mt][nt][3]);
                }
            }
            __syncthreads();
            __half* VT = aux2;                         // [DIM][N_TOK]
            for (int ch = tid; ch < 128 * 16; ch += 512) {
                const int cc = ch >> 4, sg = ch & 15;
                uint4 v = *(uint4*)&buf[cc * 136 + sg * 8];
                *(uint4*)&VT[(size_t)(colLoc + cc) * M + rowBase + sg * 8] = v;
            }
        }
    } else {  // MODE 4: fp16 split-K partial (fp32 acc, single store rounding)
        __half* C = (__half*)Cv + (size_t)blockIdx.z * M * N;
        #pragma unroll
        for (int mt = 0; mt < 2; mt++) {
            const int r0 = rowBase + wm * 32 + mt * 16 + g;
            #pragma unroll
            for (int nt = 0; nt < 4; nt++) {
                const int c = colBase + wn * 32 + nt * 8 + tg * 2;
                *(__half2*)&C[(size_t)r0 * N + c]       = __floats2half2_rn(acc[mt][nt][0], acc[mt][nt][1]);
                *(__half2*)&C[(size_t)(r0 + 8) * N + c] = __floats2half2_rn(acc[mt][nt][2], acc[mt][nt][3]);
            }
        }
    }
}

// =================== prep: weight transposes (z<3) + x round (z=3) ===================
__global__ void prep_k(const float* __restrict__ x, const float* __restrict__ w0,
                       const float* __restrict__ w1, const float* __restrict__ w2,
                       __half* __restrict__ X, __half* __restrict__ WT)
{
    const int x0 = threadIdx.x, y0 = threadIdx.y;
    if (blockIdx.z < 3) {
        __shared__ float t[32][33];
        const float* in = blockIdx.z == 0 ? w0 : (blockIdx.z == 1 ? w1 : w2);
        __half* o = WT + (size_t)blockIdx.z * DIM * DIM;
        const int c0 = blockIdx.x * 32, r0 = blockIdx.y * 32;
        #pragma unroll
        for (int j = 0; j < 32; j += 8)
            t[y0 + j][x0] = in[(size_t)(r0 + y0 + j) * DIM + c0 + x0];
        __syncthreads();
        #pragma unroll
        for (int j = 0; j < 32; j += 8)
            o[(size_t)(c0 + y0 + j) * DIM + r0 + x0] = __float2half_rn(t[x0][y0 + j]);
    } else {
        // round x -> fp16: 1024 blocks x 256 thr, 8 float4 each
        const int tid = y0 * 32 + x0;
        const int bid = blockIdx.y * 32 + blockIdx.x;
        const float4* in4 = (const float4*)x;
        #pragma unroll
        for (int r = 0; r < 8; r++) {
            const int i = (bid * 8 + r) * 256 + tid;
            float4 v = in4[i];
            __half2* o = (__half2*)(X + (size_t)i * 4);
            o[0] = __floats2half2_rn(v.x, v.y);
            o[1] = __floats2half2_rn(v.z, v.w);
        }
    }
}

// =================== out = rinv[r] * (p0+p1+p2+p3); rinv fused from spart ===================
__global__ __launch_bounds__(256)
void reduce_out(const __half* __restrict__ p, const float* __restrict__ spart,
                float* __restrict__ out)
{
    __shared__ float rinv_s[2];
    const int tid = threadIdx.x;
    const int row0 = blockIdx.x * 2;

    if (tid < 64) {
        const int w = tid >> 5, l = tid & 31;
        const int r = row0 + w;
        float s = spart[(size_t)l * N_TOK + r] + spart[(size_t)(l + 32) * N_TOK + r];
        #pragma unroll
        for (int o = 16; o; o >>= 1) s += __shfl_xor_sync(0xffffffffu, s, o);
        if (l == 0) rinv_s[w] = 1.0f / s;
    }
    __syncthreads();

    const size_t i = (size_t)blockIdx.x * 256 + tid;           // uint4 = 8 halves
    const size_t stride = (size_t)N_TOK * DIM / 8;
    const float sc = rinv_s[tid >> 7];
    const uint4* p0 = (const uint4*)p;
    uint4 u0 = p0[i], u1 = p0[i + stride], u2 = p0[i + 2 * stride], u3 = p0[i + 3 * stride];
    float4 o0, o1;
    {
        float2 a = __half22float2(*(__half2*)&u0.x), b = __half22float2(*(__half2*)&u1.x);
        float2 c = __half22float2(*(__half2*)&u2.x), d = __half22float2(*(__half2*)&u3.x);
        o0.x = (a.x + b.x + c.x + d.x) * sc; o0.y = (a.y + b.y + c.y + d.y) * sc;
    }
    {
        float2 a = __half22float2(*(__half2*)&u0.y), b = __half22float2(*(__half2*)&u1.y);
        float2 c = __half22float2(*(__half2*)&u2.y), d = __half22float2(*(__half2*)&u3.y);
        o0.z = (a.x + b.x + c.x + d.x) * sc; o0.w = (a.y + b.y + c.y + d.y) * sc;
    }
    {
        float2 a = __half22float2(*(__half2*)&u0.z), b = __half22float2(*(__half2*)&u1.z);
        float2 c = __half22float2(*(__half2*)&u2.z), d = __half22float2(*(__half2*)&u3.z);
        o1.x = (a.x + b.x + c.x + d.x) * sc; o1.y = (a.y + b.y + c.y + d.y) * sc;
    }
    {
        float2 a = __half22float2(*(__half2*)&u0.w), b = __half22float2(*(__half2*)&u1.w);
        float2 c = __half22float2(*(__half2*)&u2.w), d = __half22float2(*(__half2*)&u3.w);
        o1.z = (a.x + b.x + c.x + d.x) * sc; o1.w = (a.y + b.y + c.y + d.y) * sc;
    }
    ((float4*)out)[i * 2]     = o0;
    ((float4*)out)[i * 2 + 1] = o1;
}

// =================== host ===================
extern "C" void kernel_launch(void* const* d_in, const int* in_sizes, int n_in,
                              void* d_out, int out_size)
{
    const float* x  = (const float*)d_in[0];
    const float* Wq = (const float*)d_in[1];
    const float* Wk = (const float*)d_in[2];
    const float* Wv = (const float*)d_in[3];
    float* out = (float*)d_out;

    __half *X, *Q, *K, *VT, *WT, *S, *Opart;
    float *Spart;
    cudaGetSymbolAddress((void**)&X,     g_X);
    cudaGetSymbolAddress((void**)&Q,     g_Q);
    cudaGetSymbolAddress((void**)&K,     g_K);
    cudaGetSymbolAddress((void**)&VT,    g_VT);
    cudaGetSymbolAddress((void**)&WT,    g_WT);
    cudaGetSymbolAddress((void**)&S,     g_S);
    cudaGetSymbolAddress((void**)&Spart, g_spart);
    cudaGetSymbolAddress((void**)&Opart, g_opart);

    cudaFuncSetAttribute((const void*)gemm_h<2>, cudaFuncAttributeMaxDynamicSharedMemorySize, SMEM_BYTES);
    cudaFuncSetAttribute((const void*)gemm_h<4>, cudaFuncAttributeMaxDynamicSharedMemorySize, SMEM_BYTES);
    cudaFuncSetAttribute((const void*)gemm_h<5>, cudaFuncAttributeMaxDynamicSharedMemorySize, SMEM_BYTES);

    // prep: x -> fp16 and W -> fp16 transposed, packed [WkT|WqT|WvT], one launch
    prep_k<<<dim3(32, 32, 4), dim3(32, 8)>>>(x, Wk, Wq, Wv, X, WT);

    // fused QKV projection (reference name-swap: q = x@Wk, k = x@Wq, v = x@Wv)
    const dim3 gQKV(3 * DIM / BN, N_TOK / BM);     // (24, 64)
    gemm_h<5><<<gQKV, 512, SMEM_BYTES>>>(X, WT, Q, N_TOK, 3 * DIM, DIM, 1.f, nullptr, K, VT);

    // P = exp(QK^T / 32) fp16 + fused row partial sums
    const dim3 gScore(N_TOK / BN, N_TOK / BM);     // (64, 64)
    gemm_h<2><<<gScore, 512, SMEM_BYTES>>>(Q, K, S, N_TOK, N_TOK, DIM, 0.03125f, Spart, nullptr, nullptr);

    // PV split-K=4 -> fp16 partials, then fused rinv + reduce + normalize
    const dim3 gPV(DIM / BN, N_TOK / BM, 4);       // (8, 64, 4)
    gemm_h<4><<<gPV, 512, SMEM_BYTES>>>(S, VT, Opart, N_TOK, DIM, N_TOK, 1.f, nullptr, nullptr, nullptr);
    reduce_out<<<N_TOK / 2, 256>>>(Opart, Spart, out);
}

// round 17
// speedup vs baseline: 1.2051x; 1.0998x over previous
#include <cuda_runtime.h>
#include <cuda_fp16.h>
#include <cstdint>

#define N_TOK 8192
#define DIM   1024

// ---- fp16 mma tile config: CTA 128x128x64, 512 thr, warp 32x32, NST=3, XOR swizzle ----
#define BM 128
#define BN 128
#define BK 64
#define NST 3
#define ROWB 128                      // bytes per smem row (no padding; XOR swizzle)
#define OPB (128 * ROWB)              // 16384 B per operand per stage
#define SS  (2 * OPB)                 // 32768 B per stage
#define PIPE_BYTES (NST * SS)         // 98304 B
#define SMEM_BYTES (PIPE_BYTES + 64)  // + mbarriers

// ---- scratch (device globals; no allocation allowed) ----
__device__ __half g_X [N_TOK * DIM];
__device__ __half g_Q [N_TOK * DIM];
__device__ __half g_K [N_TOK * DIM];
__device__ __half g_VT[N_TOK * DIM];
__device__ __half g_WT[3 * DIM * DIM];                  // [WkT | WqT | WvT]
__device__ __half g_S [(size_t)N_TOK * N_TOK];
__device__ float  g_spart[(size_t)64 * N_TOK];          // score row partial sums
__device__ __half g_opart[(size_t)4 * N_TOK * DIM];     // PV split-K partials (fp16)

// =================== helpers ===================
__device__ __forceinline__ uint32_t smem_u32(const void* p) {
    uint32_t a;
    asm("{ .reg .u64 t; cvta.to.shared.u64 t, %1; cvt.u32.u64 %0, t; }" : "=r"(a) : "l"(p));
    return a;
}
__device__ __forceinline__ void cp16(uint32_t dst, const void* src) {
    asm volatile("cp.async.cg.shared.global [%0], [%1], 16;" :: "r"(dst), "l"(src));
}
__device__ __forceinline__ void mbar_init(uint32_t a, uint32_t c) {
    asm volatile("mbarrier.init.shared.b64 [%0], %1;" :: "r"(a), "r"(c) : "memory");
}
__device__ __forceinline__ void mbar_arrive(uint32_t a) {
    asm volatile("mbarrier.arrive.shared.b64 _, [%0];" :: "r"(a) : "memory");
}
__device__ __forceinline__ void cp_mbar_arrive(uint32_t a) {
    asm volatile("cp.async.mbarrier.arrive.noinc.shared.b64 [%0];" :: "r"(a) : "memory");
}
__device__ __forceinline__ void wait_parity(uint32_t mbar, uint32_t ph) {
    asm volatile(
        "{\n\t.reg .pred P;\n\t"
        "WL%=:\n\t"
        "mbarrier.try_wait.parity.acquire.cta.shared::cta.b64 P, [%0], %1, 0x989680;\n\t"
        "@P bra.uni WD%=;\n\t"
        "bra.uni WL%=;\n\t"
        "WD%=:\n\t}"
        :: "r"(mbar), "r"(ph) : "memory");
}
__device__ __forceinline__ void ldsm4(uint32_t* r, uint32_t addr) {
    asm volatile("ldmatrix.sync.aligned.m8n8.x4.shared.b16 {%0,%1,%2,%3}, [%4];"
                 : "=r"(r[0]), "=r"(r[1]), "=r"(r[2]), "=r"(r[3]) : "r"(addr));
}
__device__ __forceinline__ void mma_f16(float* c, const uint32_t* a, uint32_t b0, uint32_t b1) {
    asm volatile(
        "mma.sync.aligned.m16n8k16.row.col.f32.f16.f16.f32 "
        "{%0,%1,%2,%3}, {%4,%5,%6,%7}, {%8,%9}, {%0,%1,%2,%3};"
        : "+f"(c[0]), "+f"(c[1]), "+f"(c[2]), "+f"(c[3])
        : "r"(a[0]), "r"(a[1]), "r"(a[2]), "r"(a[3]), "r"(b0), "r"(b1));
}

// =================== fp16 mma.sync GEMM (512 thr, warp 32x32, BK=64, XOR swizzle) ===================
// acc = A[M,K_slice] @ B[N,K_slice]^T  (K sliced by gridDim.z)
// MODE 2: C fp16 = exp(alpha*acc); fused row partial sums -> spart
// MODE 4: partial[z] fp16 = acc                 (PV split-K)
// MODE 5: fused QKV projection. blockIdx.x>>3 selects output:
//         0 -> Q fp16, 1 -> K fp16, 2 -> VT fp16 (smem-transposed epilogue).
template<int MODE>
__global__ __launch_bounds__(512, 2)
void gemm_h(const __half* __restrict__ A, const __half* __restrict__ B,
            void* __restrict__ Cv, int M, int N, int K,
            float alpha, float* __restrict__ spart,
            __half* __restrict__ aux1, __half* __restrict__ aux2)
{
    extern __shared__ char smraw[];
    const uint32_t sbase = smem_u32(smraw);
    const uint32_t mb = sbase + PIPE_BYTES;    // full[s]@mb+16s, empty[s]@mb+16s+8
    const int tid  = threadIdx.x;
    const int wid  = tid >> 5, lane = tid & 31;
    const int wm   = wid & 3, wn = wid >> 2;        // 4 x 4 warp grid
    const int rowBase = blockIdx.y * BM;
    const int colBase = blockIdx.x * BN;
    const int kPer = K / gridDim.z;
    const int kOff = blockIdx.z * kPer;
    const int nk = kPer / BK;

    if (tid == 0) {
        #pragma unroll
        for (int s = 0; s < NST; s++) {
            mbar_init(mb + 16 * s, 512);      // full
            mbar_init(mb + 16 * s + 8, 512);  // empty
        }
    }
    __syncthreads();

    // ---- gmem -> smem: 128B rows, 8 x 16B chunks, chunk ^= row&7 ----
    const int gr = tid >> 3;                 // 0..63
    const int seg = tid & 7;                 // 0..7
    const __half* gA = A + (size_t)(rowBase + gr) * K + kOff + seg * 8;
    const __half* gB = B + (size_t)(colBase + gr) * K + kOff + seg * 8;
    const size_t hop = (size_t)64 * K;
    const uint32_t swc = (uint32_t)(seg ^ (gr & 7)) * 16;   // same xor for row gr+64
    const uint32_t dA = sbase + (uint32_t)gr * ROWB + swc;
    const uint32_t dB = dA + OPB;

    // ---- ldmatrix: per-lane row bases + per-kk xor chunk offsets ----
    const int quad = lane >> 3, lr = lane & 7;
    const int qh = quad >> 1;
    uint32_t aBase[2], bBase[2], xoff[4];
    #pragma unroll
    for (int mt = 0; mt < 2; mt++) {
        int r = wm * 32 + mt * 16 + (quad & 1) * 8 + lr;
        aBase[mt] = sbase + (uint32_t)r * ROWB;
    }
    #pragma unroll
    for (int p = 0; p < 2; p++) {
        int r = wn * 32 + p * 16 + (quad & 1) * 8 + lr;
        bBase[p] = sbase + OPB + (uint32_t)r * ROWB;
    }
    #pragma unroll
    for (int kk = 0; kk < 4; kk++)
        xoff[kk] = (uint32_t)(((kk * 2 + qh) ^ lr) * 16);

    float acc[2][4][4];
    #pragma unroll
    for (int i = 0; i < 2; i++)
        #pragma unroll
        for (int j = 0; j < 4; j++)
            #pragma unroll
            for (int e = 0; e < 4; e++) acc[i][j][e] = 0.f;

    // ---- prologue: fill NST-1 stages ----
    #pragma unroll
    for (int s = 0; s < NST - 1; s++) {
        cp16(dA + s * SS,             gA);
        cp16(dA + s * SS + 64 * ROWB, gA + hop);
        cp16(dB + s * SS,             gB);
        cp16(dB + s * SS + 64 * ROWB, gB + hop);
        cp_mbar_arrive(mb + 16 * s);
        gA += BK; gB += BK;
    }

    // ---- main loop: no block barriers; warps drift across stages ----
    int pS = NST - 1, pPh = 1;     // producer cursor
    int cS = 0, cPh = 0;           // consumer cursor
    for (int it = 0; it < nk; it++) {
        const int w = it + NST - 1;
        if (w < nk) {
            if (w >= NST)                      // stage previously used: wait consumers
                wait_parity(mb + 16 * pS + 8, pPh);
            cp16(dA + pS * SS,             gA);
            cp16(dA + pS * SS + 64 * ROWB, gA + hop);
            cp16(dB + pS * SS,             gB);
            cp16(dB + pS * SS + 64 * ROWB, gB + hop);
            cp_mbar_arrive(mb + 16 * pS);
            gA += BK; gB += BK;
            if (++pS == NST) { pS = 0; pPh ^= 1; }
        }

        wait_parity(mb + 16 * cS, cPh);        // stage data ready
        const uint32_t st = (uint32_t)(cS * SS);
        #pragma unroll
        for (int kk = 0; kk < 4; kk++) {       // 4 x k16 per stage
            const uint32_t off = st + xoff[kk];
            uint32_t a[2][4], b[2][4];
            #pragma unroll
            for (int mt = 0; mt < 2; mt++) ldsm4(a[mt], aBase[mt] + off);
            #pragma unroll
            for (int p = 0; p < 2; p++)    ldsm4(b[p],  bBase[p] + off);
            #pragma unroll
            for (int mt = 0; mt < 2; mt++)
                #pragma unroll
                for (int p = 0; p < 2; p++) {
                    mma_f16(acc[mt][2*p],   a[mt], b[p][0], b[p][2]);
                    mma_f16(acc[mt][2*p+1], a[mt], b[p][1], b[p][3]);
                }
        }
        mbar_arrive(mb + 16 * cS + 8);         // release stage for overwrite
        if (++cS == NST) { cS = 0; cPh ^= 1; }
    }

    // ---- epilogue ----
    const int g = lane >> 2, tg = lane & 3;

    if (MODE == 2) {
        float rs0[2] = {0.f, 0.f};
        float rs1[2] = {0.f, 0.f};
        __half* C = (__half*)Cv;
        #pragma unroll
        for (int mt = 0; mt < 2; mt++) {
            const int r0 = rowBase + wm * 32 + mt * 16 + g;
            #pragma unroll
            for (int nt = 0; nt < 4; nt++) {
                const int c = colBase + wn * 32 + nt * 8 + tg * 2;
                float v0 = __expf(alpha * acc[mt][nt][0]);
                float v1 = __expf(alpha * acc[mt][nt][1]);
                float v2 = __expf(alpha * acc[mt][nt][2]);
                float v3 = __expf(alpha * acc[mt][nt][3]);
                rs0[mt] += v0 + v1;
                rs1[mt] += v2 + v3;
                *(__half2*)&C[(size_t)r0 * N + c]       = __floats2half2_rn(v0, v1);
                *(__half2*)&C[(size_t)(r0 + 8) * N + c] = __floats2half2_rn(v2, v3);
            }
        }
        // reduce over tg lanes, then across the 4 wn warps via smem
        float* part = (float*)smraw;           // [4][128]
        __syncthreads();                       // all warps out of mainloop
        #pragma unroll
        for (int mt = 0; mt < 2; mt++) {
            float a0 = rs0[mt], a1 = rs1[mt];
            a0 += __shfl_xor_sync(0xffffffffu, a0, 1);
            a0 += __shfl_xor_sync(0xffffffffu, a0, 2);
            a1 += __shfl_xor_sync(0xffffffffu, a1, 1);
            a1 += __shfl_xor_sync(0xffffffffu, a1, 2);
            if (tg == 0) {
                part[wn * 128 + wm * 32 + mt * 16 + g]     = a0;
                part[wn * 128 + wm * 32 + mt * 16 + g + 8] = a1;
            }
        }
        __syncthreads();
        if (tid < 128) {
            float s = part[tid] + part[128 + tid] + part[256 + tid] + part[384 + tid];
            spart[(size_t)blockIdx.x * M + rowBase + tid] = s;
        }
    } else if (MODE == 5) {
        const int grp = blockIdx.x >> 3;               // 0=Q, 1=K, 2=VT
        const int colLoc = (blockIdx.x & 7) * BN;      // column within 1024
        if (grp < 2) {
            __half* C = grp == 0 ? (__half*)Cv : aux1;
            #pragma unroll
            for (int mt = 0; mt < 2; mt++) {
                const int r0 = rowBase + wm * 32 + mt * 16 + g;
                #pragma unroll
                for (int nt = 0; nt < 4; nt++) {
                    const int c = colLoc + wn * 32 + nt * 8 + tg * 2;
                    *(__half2*)&C[(size_t)r0 * DIM + c] =
                        __floats2half2_rn(acc[mt][nt][0], acc[mt][nt][1]);
                    *(__half2*)&C[(size_t)(r0 + 8) * DIM + c] =
                        __floats2half2_rn(acc[mt][nt][2], acc[mt][nt][3]);
                }
            }
        } else {
            __half* buf = (__half*)smraw;              // [128 cols][136 rows]
            __syncthreads();                           // all warps out of mainloop
            #pragma unroll
            for (int mt = 0; mt < 2; mt++) {
                const int r0 = wm * 32 + mt * 16 + g;
                #pragma unroll
                for (int nt = 0; nt < 4; nt++) {
                    const int c = wn * 32 + nt * 8 + tg * 2;
                    buf[(c    ) * 136 + r0    ] = __float2half_rn(acc[mt][nt][0]);
                    buf[(c + 1) * 136 + r0    ] = __float2half_rn(acc[mt][nt][1]);
                    buf[(c    ) * 136 + r0 + 8] = __float2half_rn(acc[mt][nt][2]);
                    buf[(c + 1) * 136 + r0 + 8] = __float2half_rn(acc[mt][nt][3]);
                }
            }
            __syncthreads();
            __half* VT = aux2;                         // [DIM][N_TOK]
            for (int ch = tid; ch < 128 * 16; ch += 512) {
                const int cc = ch >> 4, sg = ch & 15;
                uint4 v = *(uint4*)&buf[cc * 136 + sg * 8];
                *(uint4*)&VT[(size_t)(colLoc + cc) * M + rowBase + sg * 8] = v;
            }
        }
    } else {  // MODE 4: fp16 split-K partial (fp32 acc, single store rounding)
        __half* C = (__half*)Cv + (size_t)blockIdx.z * M * N;
        #pragma unroll
        for (int mt = 0; mt < 2; mt++) {
            const int r0 = rowBase + wm * 32 + mt * 16 + g;
            #pragma unroll
            for (int nt = 0; nt < 4; nt++) {
                const int c = colBase + wn * 32 + nt * 8 + tg * 2;
                *(__half2*)&C[(size_t)r0 * N + c]       = __floats2half2_rn(acc[mt][nt][0], acc[mt][nt][1]);
                *(__half2*)&C[(size_t)(r0 + 8) * N + c] = __floats2half2_rn(acc[mt][nt][2], acc[mt][nt][3]);
            }
        }
    }
}

// =================== prep: weight transposes (z<3) + x round (z=3) ===================
__global__ void prep_k(const float* __restrict__ x, const float* __restrict__ w0,
                       const float* __restrict__ w1, const float* __restrict__ w2,
                       __half* __restrict__ X, __half* __restrict__ WT)
{
    const int x0 = threadIdx.x, y0 = threadIdx.y;
    if (blockIdx.z < 3) {
        __shared__ float t[32][33];
        const float* in = blockIdx.z == 0 ? w0 : (blockIdx.z == 1 ? w1 : w2);
        __half* o = WT + (size_t)blockIdx.z * DIM * DIM;
        const int c0 = blockIdx.x * 32, r0 = blockIdx.y * 32;
        #pragma unroll
        for (int j = 0; j < 32; j += 8)
            t[y0 + j][x0] = in[(size_t)(r0 + y0 + j) * DIM + c0 + x0];
        __syncthreads();
        #pragma unroll
        for (int j = 0; j < 32; j += 8)
            o[(size_t)(c0 + y0 + j) * DIM + r0 + x0] = __float2half_rn(t[x0][y0 + j]);
    } else {
        // round x -> fp16: 1024 blocks x 256 thr, 8 float4 each
        const int tid = y0 * 32 + x0;
        const int bid = blockIdx.y * 32 + blockIdx.x;
        const float4* in4 = (const float4*)x;
        #pragma unroll
        for (int r = 0; r < 8; r++) {
            const int i = (bid * 8 + r) * 256 + tid;
            float4 v = in4[i];
            __half2* o = (__half2*)(X + (size_t)i * 4);
            o[0] = __floats2half2_rn(v.x, v.y);
            o[1] = __floats2half2_rn(v.z, v.w);
        }
    }
}

// =================== out = rinv[r] * (p0+p1+p2+p3); rinv fused from spart ===================
__global__ __launch_bounds__(256)
void reduce_out(const __half* __restrict__ p, const float* __restrict__ spart,
                float* __restrict__ out)
{
    __shared__ float rinv_s[2];
    const int tid = threadIdx.x;
    const int row0 = blockIdx.x * 2;

    if (tid < 64) {
        const int w = tid >> 5, l = tid & 31;
        const int r = row0 + w;
        float s = spart[(size_t)l * N_TOK + r] + spart[(size_t)(l + 32) * N_TOK + r];
        #pragma unroll
        for (int o = 16; o; o >>= 1) s += __shfl_xor_sync(0xffffffffu, s, o);
        if (l == 0) rinv_s[w] = 1.0f / s;
    }
    __syncthreads();

    const size_t i = (size_t)blockIdx.x * 256 + tid;           // uint4 = 8 halves
    const size_t stride = (size_t)N_TOK * DIM / 8;
    const float sc = rinv_s[tid >> 7];
    const uint4* p0 = (const uint4*)p;
    uint4 u0 = p0[i], u1 = p0[i + stride], u2 = p0[i + 2 * stride], u3 = p0[i + 3 * stride];
    float4 o0, o1;
    {
        float2 a = __half22float2(*(__half2*)&u0.x), b = __half22float2(*(__half2*)&u1.x);
        float2 c = __half22float2(*(__half2*)&u2.x), d = __half22float2(*(__half2*)&u3.x);
        o0.x = (a.x + b.x + c.x + d.x) * sc; o0.y = (a.y + b.y + c.y + d.y) * sc;
    }
    {
        float2 a = __half22float2(*(__half2*)&u0.y), b = __half22float2(*(__half2*)&u1.y);
        float2 c = __half22float2(*(__half2*)&u2.y), d = __half22float2(*(__half2*)&u3.y);
        o0.z = (a.x + b.x + c.x + d.x) * sc; o0.w = (a.y + b.y + c.y + d.y) * sc;
    }
    {
        float2 a = __half22float2(*(__half2*)&u0.z), b = __half22float2(*(__half2*)&u1.z);
        float2 c = __half22float2(*(__half2*)&u2.z), d = __half22float2(*(__half2*)&u3.z);
        o1.x = (a.x + b.x + c.x + d.x) * sc; o1.y = (a.y + b.y + c.y + d.y) * sc;
    }
    {
        float2 a = __half22float2(*(__half2*)&u0.w), b = __half22float2(*(__half2*)&u1.w);
        float2 c = __half22float2(*(__half2*)&u2.w), d = __half22float2(*(__half2*)&u3.w);
        o1.z = (a.x + b.x + c.x + d.x) * sc; o1.w = (a.y + b.y + c.y + d.y) * sc;
    }
    ((float4*)out)[i * 2]     = o0;
    ((float4*)out)[i * 2 + 1] = o1;
}

// =================== host ===================
extern "C" void kernel_launch(void* const* d_in, const int* in_sizes, int n_in,
                              void* d_out, int out_size)
{
    const float* x  = (const float*)d_in[0];
    const float* Wq = (const float*)d_in[1];
    const float* Wk = (const float*)d_in[2];
    const float* Wv = (const float*)d_in[3];
    float* out = (float*)d_out;

    __half *X, *Q, *K, *VT, *WT, *S, *Opart;
    float *Spart;
    cudaGetSymbolAddress((void**)&X,     g_X);
    cudaGetSymbolAddress((void**)&Q,     g_Q);
    cudaGetSymbolAddress((void**)&K,     g_K);
    cudaGetSymbolAddress((void**)&VT,    g_VT);
    cudaGetSymbolAddress((void**)&WT,    g_WT);
    cudaGetSymbolAddress((void**)&S,     g_S);
    cudaGetSymbolAddress((void**)&Spart, g_spart);
    cudaGetSymbolAddress((void**)&Opart, g_opart);

    cudaFuncSetAttribute((const void*)gemm_h<2>, cudaFuncAttributeMaxDynamicSharedMemorySize, SMEM_BYTES);
    cudaFuncSetAttribute((const void*)gemm_h<4>, cudaFuncAttributeMaxDynamicSharedMemorySize, SMEM_BYTES);
    cudaFuncSetAttribute((const void*)gemm_h<5>, cudaFuncAttributeMaxDynamicSharedMemorySize, SMEM_BYTES);

    // prep: x -> fp16 and W -> fp16 transposed, packed [WkT|WqT|WvT], one launch
    prep_k<<<dim3(32, 32, 4), dim3(32, 8)>>>(x, Wk, Wq, Wv, X, WT);

    // fused QKV projection (reference name-swap: q = x@Wk, k = x@Wq, v = x@Wv)
    const dim3 gQKV(3 * DIM / BN, N_TOK / BM);     // (24, 64)
    gemm_h<5><<<gQKV, 512, SMEM_BYTES>>>(X, WT, Q, N_TOK, 3 * DIM, DIM, 1.f, nullptr, K, VT);

    // P = exp(QK^T / 32) fp16 + fused row partial sums
    const dim3 gScore(N_TOK / BN, N_TOK / BM);     // (64, 64)
    gemm_h<2><<<gScore, 512, SMEM_BYTES>>>(Q, K, S, N_TOK, N_TOK, DIM, 0.03125f, Spart, nullptr, nullptr);

    // PV split-K=4 -> fp16 partials, then fused rinv + reduce + normalize
    const dim3 gPV(DIM / BN, N_TOK / BM, 4);       // (8, 64, 4)
    gemm_h<4><<<gPV, 512, SMEM_BYTES>>>(S, VT, Opart, N_TOK, DIM, N_TOK, 1.f, nullptr, nullptr, nullptr);
    reduce_out<<<N_TOK / 2, 256>>>(Opart, Spart, out);
}